// round 1
// baseline (speedup 1.0000x reference)
#include <cuda_runtime.h>
#include <cuda_bf16.h>

// Problem constants
#define NN   64
#define LL   1024
#define DD   512
#define LI_  1022
#define SS   127
#define OUTC 300
#define EPSF 1e-5f

// Scratch for span means (allocation-free rule: __device__ global)
__device__ float g_means[(size_t)NN * SS * DD];

// ---------------------------------------------------------------------------
// Kernel 1: span means + copy of `use = t1[:,0,:]`
// grid = NN*SS blocks, 128 threads; each thread handles one float4 of D=512.
// ---------------------------------------------------------------------------
__global__ void means_kernel(const float* __restrict__ t1,
                             const int* __restrict__ ws32,
                             float* __restrict__ out_use)
{
    int b = blockIdx.x;            // 0 .. NN*SS-1
    int n = b / SS;
    int s = b - n * SS;

    // word_seq dtype detection (int32 vs int64 storage).
    // int32 layout: [0,8,8,16,...]  -> ws32[1]=8, ws32[3]=16
    // int64 layout: [0,0,8,0,8,0,16,0,...] -> ws32[1]=0, ws32[3]=0
    bool is64 = (ws32[1] == 0 && ws32[3] == 0);
    long long start, end;
    if (is64) {
        const long long* ws64 = (const long long*)ws32;
        start = ws64[(size_t)(n * SS + s) * 2];
        end   = ws64[(size_t)(n * SS + s) * 2 + 1];
    } else {
        start = ws32[(size_t)(n * SS + s) * 2];
        end   = ws32[(size_t)(n * SS + s) * 2 + 1];
    }
    if (start > (long long)(LI_ - 1)) start = LI_ - 1;
    if (end   > (long long)LI_)       end   = LI_;
    int cnt = (int)(end - start);

    int d4 = threadIdx.x;          // 0..127 -> float4 slot
    const float4* base =
        (const float4*)(t1 + ((size_t)n * LL + 1 + (size_t)start) * DD) + d4;

    float4 acc = make_float4(0.f, 0.f, 0.f, 0.f);
    for (int r = 0; r < cnt; ++r) {
        float4 v = base[(size_t)r * (DD / 4)];
        acc.x += v.x; acc.y += v.y; acc.z += v.z; acc.w += v.w;
    }
    float inv = 1.0f / (float)cnt;
    acc.x *= inv; acc.y *= inv; acc.z *= inv; acc.w *= inv;
    ((float4*)(g_means + (size_t)b * DD))[d4] = acc;

    // fold in the `use` copy (t1[:,0,:]) once per n
    if (s == 0) {
        ((float4*)(out_use + (size_t)n * DD))[d4] =
            ((const float4*)(t1 + (size_t)n * LL * DD))[d4];
    }
}

// ---------------------------------------------------------------------------
// Kernel 2: GEMM h = means @ W^T + b, fused LayerNorm over OUT=300.
// Block = 256 threads, tile BM=64 rows x all 300 cols, BK=16.
// Thread micro-tile: 8 rows x 10 cols (warp w owns rows w*8..w*8+7,
// lane owns cols lane+32*j).
// ---------------------------------------------------------------------------
#define BM 64
#define BK 16

__global__ __launch_bounds__(256, 1)
void gemm_ln_kernel(const float* __restrict__ W,      // [300,512] row-major
                    const float* __restrict__ blin,   // [300]
                    const float* __restrict__ gamma,  // [300]
                    const float* __restrict__ beta,   // [300]
                    float* __restrict__ out)          // [8128,300]
{
    __shared__ float sA[BK][BM + 1];     // +1 pad (store-phase conflicts)
    __shared__ float sB[320][BK + 1];    // 320 rows (cols >=300 zero-filled)

    int t    = threadIdx.x;
    int w    = t >> 5;     // warp 0..7
    int lane = t & 31;
    int rowBase = blockIdx.x * BM;

    float acc[8][10];
#pragma unroll
    for (int i = 0; i < 8; i++)
#pragma unroll
        for (int j = 0; j < 10; j++) acc[i][j] = 0.f;

    const float* Ablk = g_means + (size_t)rowBase * DD;

    for (int kc = 0; kc < DD; kc += BK) {
        // stage A: 64x16 floats (coalesced: 16 consecutive k per row)
#pragma unroll
        for (int i = 0; i < 4; i++) {
            int lin = t + 256 * i;
            int r = lin >> 4;
            int k = lin & 15;
            sA[k][r] = Ablk[(size_t)r * DD + kc + k];
        }
        // stage B: 320x16 floats, zero-fill beyond 300 cols
#pragma unroll
        for (int i = 0; i < 20; i++) {
            int lin = t + 256 * i;
            int c = lin >> 4;
            int k = lin & 15;
            sB[c][k] = (c < OUTC) ? W[(size_t)c * DD + kc + k] : 0.f;
        }
        __syncthreads();

#pragma unroll
        for (int k = 0; k < BK; k++) {
            float a[8], bb[10];
#pragma unroll
            for (int i = 0; i < 8; i++) a[i] = sA[k][w * 8 + i];   // broadcast
#pragma unroll
            for (int j = 0; j < 10; j++) bb[j] = sB[lane + 32 * j][k]; // cf-free
#pragma unroll
            for (int i = 0; i < 8; i++)
#pragma unroll
                for (int j = 0; j < 10; j++)
                    acc[i][j] = fmaf(a[i], bb[j], acc[i][j]);
        }
        __syncthreads();
    }

    // epilogue: bias + per-row LayerNorm (warp-level, 8 rows per warp)
#pragma unroll
    for (int i = 0; i < 8; i++) {
        float sum = 0.f, sq = 0.f;
#pragma unroll
        for (int j = 0; j < 10; j++) {
            int c = lane + 32 * j;
            if (c < OUTC) {
                float v = acc[i][j] + blin[c];
                acc[i][j] = v;
                sum += v;
                sq  += v * v;
            }
        }
#pragma unroll
        for (int off = 16; off; off >>= 1) {
            sum += __shfl_xor_sync(0xffffffffu, sum, off);
            sq  += __shfl_xor_sync(0xffffffffu, sq,  off);
        }
        float mu  = sum * (1.0f / OUTC);
        float var = sq * (1.0f / OUTC) - mu * mu;
        float inv = rsqrtf(var + EPSF);

        int row = rowBase + w * 8 + i;
        float* o = out + (size_t)row * OUTC;
#pragma unroll
        for (int j = 0; j < 10; j++) {
            int c = lane + 32 * j;
            if (c < OUTC)
                o[c] = (acc[i][j] - mu) * inv * gamma[c] + beta[c];
        }
    }
}

// ---------------------------------------------------------------------------
// Inputs (metadata order): t1, word_seq, key_padding_mask, w_lin, b_lin,
// gamma, beta.  Output: tuple (out[64,127,300], use[64,512]) concatenated.
// ---------------------------------------------------------------------------
extern "C" void kernel_launch(void* const* d_in, const int* in_sizes, int n_in,
                              void* d_out, int out_size)
{
    const float* t1    = (const float*)d_in[0];
    const int*   ws    = (const int*)  d_in[1];
    const float* W     = (const float*)d_in[3];
    const float* blin  = (const float*)d_in[4];
    const float* gamma = (const float*)d_in[5];
    const float* beta  = (const float*)d_in[6];

    float* out = (float*)d_out;
    float* use = out + (size_t)NN * SS * OUTC;

    means_kernel<<<NN * SS, 128>>>(t1, ws, use);
    gemm_ln_kernel<<<SS, 256>>>(W, blin, gamma, beta, out);
}

// round 2
// speedup vs baseline: 1.1694x; 1.1694x over previous
#include <cuda_runtime.h>
#include <cuda_bf16.h>

// Problem constants
#define NN   64
#define LL   1024
#define DD   512
#define LI_  1022
#define SS   127
#define OUTC 300
#define EPSF 1e-5f

// Scratch for span means (allocation-free rule: __device__ global)
__device__ float g_means[(size_t)NN * SS * DD];

// packed fp32x2 FMA (Blackwell FFMA2 — PTX only)
#define FMA_F32X2(d, a, b, c) \
    asm("fma.rn.f32x2 %0, %1, %2, %3;" : "=l"(d) : "l"(a), "l"(b), "l"(c))
#define PACK_DUP_F32X2(d, s) \
    asm("mov.b64 %0, {%1, %1};" : "=l"(d) : "r"(__float_as_uint(s)))
#define UNPACK_F32X2(lo, hi, v) \
    asm("mov.b64 {%0, %1}, %2;" : "=f"(lo), "=f"(hi) : "l"(v))

// ---------------------------------------------------------------------------
// Kernel 1: span means + copy of `use = t1[:,0,:]`
// grid = NN*SS blocks, 128 threads; each thread handles one float4 of D=512.
// ---------------------------------------------------------------------------
__global__ void means_kernel(const float* __restrict__ t1,
                             const int* __restrict__ ws32,
                             float* __restrict__ out_use)
{
    int b = blockIdx.x;            // 0 .. NN*SS-1
    int n = b / SS;
    int s = b - n * SS;

    // word_seq dtype detection (int32 vs int64 storage).
    bool is64 = (ws32[1] == 0 && ws32[3] == 0);
    long long start, end;
    if (is64) {
        const long long* ws64 = (const long long*)ws32;
        start = ws64[(size_t)(n * SS + s) * 2];
        end   = ws64[(size_t)(n * SS + s) * 2 + 1];
    } else {
        start = ws32[(size_t)(n * SS + s) * 2];
        end   = ws32[(size_t)(n * SS + s) * 2 + 1];
    }
    if (start > (long long)(LI_ - 1)) start = LI_ - 1;
    if (end   > (long long)LI_)       end   = LI_;
    int cnt = (int)(end - start);

    int d4 = threadIdx.x;          // 0..127 -> float4 slot
    const float4* base =
        (const float4*)(t1 + ((size_t)n * LL + 1 + (size_t)start) * DD) + d4;

    float4 acc = make_float4(0.f, 0.f, 0.f, 0.f);
    if (cnt == 8) {
        // fast path: full unroll -> 8 independent in-flight loads (MLP=8)
        float4 v[8];
#pragma unroll
        for (int r = 0; r < 8; ++r) v[r] = base[(size_t)r * (DD / 4)];
#pragma unroll
        for (int r = 0; r < 8; ++r) {
            acc.x += v[r].x; acc.y += v[r].y; acc.z += v[r].z; acc.w += v[r].w;
        }
    } else {
        for (int r = 0; r < cnt; ++r) {
            float4 v = base[(size_t)r * (DD / 4)];
            acc.x += v.x; acc.y += v.y; acc.z += v.z; acc.w += v.w;
        }
    }
    float inv = 1.0f / (float)cnt;
    acc.x *= inv; acc.y *= inv; acc.z *= inv; acc.w *= inv;
    ((float4*)(g_means + (size_t)b * DD))[d4] = acc;

    // fold in the `use` copy (t1[:,0,:]) once per n
    if (s == 0) {
        ((float4*)(out_use + (size_t)n * DD))[d4] =
            ((const float4*)(t1 + (size_t)n * LL * DD))[d4];
    }
}

// ---------------------------------------------------------------------------
// Kernel 2: GEMM h = means @ W^T + b, fused LayerNorm over OUT=300.
// Block = 256 threads, tile BM=64 rows x all 300 cols, BK=16.
// Thread micro-tile: 4 row-PAIRS x 10 cols using fma.rn.f32x2:
//   warp w owns rows w*8..w*8+7; each thread holds rows {w*8+2i, w*8+2i+1}
//   packed in the f32x2 lanes; col operand duplicated {b,b}.
// ---------------------------------------------------------------------------
#define BM 64
#define BK 16
#define SA_STRIDE 66   // conflict-free stores + 8B alignment of even cols

__global__ __launch_bounds__(256, 1)
void gemm_ln_kernel(const float* __restrict__ W,      // [300,512] row-major
                    const float* __restrict__ blin,   // [300]
                    const float* __restrict__ gamma,  // [300]
                    const float* __restrict__ beta,   // [300]
                    float* __restrict__ out)          // [8128,300]
{
    __shared__ float sA[BK][SA_STRIDE];  // [k][row], rows contiguous
    __shared__ float sB[320][BK + 1];    // 320 rows (cols >=300 zero-filled)

    int t    = threadIdx.x;
    int w    = t >> 5;     // warp 0..7
    int lane = t & 31;
    int rowBase = blockIdx.x * BM;

    unsigned long long acc2[4][10];
#pragma unroll
    for (int i = 0; i < 4; i++)
#pragma unroll
        for (int j = 0; j < 10; j++) acc2[i][j] = 0ull;

    const float* Ablk = g_means + (size_t)rowBase * DD;

    for (int kc = 0; kc < DD; kc += BK) {
        // stage A: 64x16 floats (coalesced: 16 consecutive k per row)
#pragma unroll
        for (int i = 0; i < 4; i++) {
            int lin = t + 256 * i;
            int r = lin >> 4;
            int k = lin & 15;
            sA[k][r] = Ablk[(size_t)r * DD + kc + k];
        }
        // stage B: 320x16 floats, zero-fill beyond 300 cols
#pragma unroll
        for (int i = 0; i < 20; i++) {
            int lin = t + 256 * i;
            int c = lin >> 4;
            int k = lin & 15;
            sB[c][k] = (c < OUTC) ? W[(size_t)c * DD + kc + k] : 0.f;
        }
        __syncthreads();

#pragma unroll
        for (int k = 0; k < BK; k++) {
            unsigned long long a2[4], b2[10];
#pragma unroll
            for (int i = 0; i < 4; i++)   // LDS.64, warp-broadcast, rows 2i,2i+1
                a2[i] = *reinterpret_cast<const unsigned long long*>(
                            &sA[k][w * 8 + 2 * i]);
#pragma unroll
            for (int j = 0; j < 10; j++) {
                float b = sB[lane + 32 * j][k];     // conflict-free LDS.32
                PACK_DUP_F32X2(b2[j], b);
            }
#pragma unroll
            for (int i = 0; i < 4; i++)
#pragma unroll
                for (int j = 0; j < 10; j++)
                    FMA_F32X2(acc2[i][j], a2[i], b2[j], acc2[i][j]);
        }
        __syncthreads();
    }

    // epilogue: bias + per-row LayerNorm (warp-level; pair = rows 2i, 2i+1)
#pragma unroll
    for (int i = 0; i < 4; i++) {
        float vL[10], vH[10];
        float sumL = 0.f, sqL = 0.f, sumH = 0.f, sqH = 0.f;
#pragma unroll
        for (int j = 0; j < 10; j++) {
            int c = lane + 32 * j;
            float lo, hi;
            UNPACK_F32X2(lo, hi, acc2[i][j]);
            if (c < OUTC) {
                float bb = blin[c];
                lo += bb; hi += bb;
                vL[j] = lo; vH[j] = hi;
                sumL += lo; sqL += lo * lo;
                sumH += hi; sqH += hi * hi;
            }
        }
#pragma unroll
        for (int off = 16; off; off >>= 1) {
            sumL += __shfl_xor_sync(0xffffffffu, sumL, off);
            sqL  += __shfl_xor_sync(0xffffffffu, sqL,  off);
            sumH += __shfl_xor_sync(0xffffffffu, sumH, off);
            sqH  += __shfl_xor_sync(0xffffffffu, sqH,  off);
        }
        float muL  = sumL * (1.0f / OUTC);
        float invL = rsqrtf(sqL * (1.0f / OUTC) - muL * muL + EPSF);
        float muH  = sumH * (1.0f / OUTC);
        float invH = rsqrtf(sqH * (1.0f / OUTC) - muH * muH + EPSF);

        int rowL = rowBase + w * 8 + 2 * i;
        float* oL = out + (size_t)rowL * OUTC;
        float* oH = oL + OUTC;
#pragma unroll
        for (int j = 0; j < 10; j++) {
            int c = lane + 32 * j;
            if (c < OUTC) {
                float g = gamma[c], be = beta[c];
                oL[c] = (vL[j] - muL) * invL * g + be;
                oH[c] = (vH[j] - muH) * invH * g + be;
            }
        }
    }
}

// ---------------------------------------------------------------------------
// Inputs (metadata order): t1, word_seq, key_padding_mask, w_lin, b_lin,
// gamma, beta.  Output: tuple (out[64,127,300], use[64,512]) concatenated.
// ---------------------------------------------------------------------------
extern "C" void kernel_launch(void* const* d_in, const int* in_sizes, int n_in,
                              void* d_out, int out_size)
{
    const float* t1    = (const float*)d_in[0];
    const int*   ws    = (const int*)  d_in[1];
    const float* W     = (const float*)d_in[3];
    const float* blin  = (const float*)d_in[4];
    const float* gamma = (const float*)d_in[5];
    const float* beta  = (const float*)d_in[6];

    float* out = (float*)d_out;
    float* use = out + (size_t)NN * SS * OUTC;

    means_kernel<<<NN * SS, 128>>>(t1, ws, use);
    gemm_ln_kernel<<<SS, 256>>>(W, blin, gamma, beta, out);
}